// round 16
// baseline (speedup 1.0000x reference)
#include <cuda_runtime.h>
#include <cuda_fp16.h>
#include <math.h>
#include <stdint.h>

// Problem constants
static constexpr int Bb  = 8;
static constexpr int Tt  = 1024;
static constexpr int Uu  = 512;
static constexpr int DH  = 64;
static constexpr int HB  = 64;           // H*B
static constexpr int MR  = Bb * Tt;      // 8192 rows

// Scratch (device globals)
__device__ __half g_a16[3][(size_t)MR * Uu];     // q,k,v inputs fp16
__device__ __half g_wt16[4][(size_t)Uu * Uu];    // W^T (n-major, k contiguous) fp16
__device__ __half g_qh16[(size_t)HB * Tt * DH];  // head-split, pre-scaled 1/8
__device__ __half g_kh16[(size_t)HB * Tt * DH];  // head-split [hb][t][d]
__device__ __half g_vt16[(size_t)HB * DH * Tt];  // head-split TRANSPOSED [hb][d][t]
__device__ __half g_att16[(size_t)MR * Uu];      // attention out, merged

// ---------------------------------------------------------------------------
// Helpers
// ---------------------------------------------------------------------------
__device__ __forceinline__ void mma_f16(float c[4], const uint32_t a[4], const uint32_t b[2]) {
    asm volatile(
        "mma.sync.aligned.m16n8k16.row.col.f32.f16.f16.f32 "
        "{%0,%1,%2,%3}, {%4,%5,%6,%7}, {%8,%9}, {%0,%1,%2,%3};"
        : "+f"(c[0]), "+f"(c[1]), "+f"(c[2]), "+f"(c[3])
        : "r"(a[0]), "r"(a[1]), "r"(a[2]), "r"(a[3]), "r"(b[0]), "r"(b[1]));
}

__device__ __forceinline__ void cp16(uint32_t saddr, const void* gptr) {
    asm volatile("cp.async.cg.shared.global [%0], [%1], 16;" :: "r"(saddr), "l"(gptr));
}

__device__ __forceinline__ uint32_t smem_u32(const void* p) {
    uint32_t a;
    asm("{ .reg .u64 t; cvta.to.shared.u64 t, %1; cvt.u32.u64 %0, t; }" : "=r"(a) : "l"(p));
    return a;
}

// pack two fp32 -> f16x2 in a b32 register (RN rounding)
__device__ __forceinline__ uint32_t packh2(float x, float y) {
    uint32_t r;
    asm("cvt.rn.f16x2.f32 %0, %1, %2;" : "=r"(r) : "f"(y), "f"(x));
    return r;
}

// ---------------------------------------------------------------------------
// Input conversion: q/k/v fp32 -> fp16 (grid.y = z)
// ---------------------------------------------------------------------------
__global__ __launch_bounds__(512) void cvt_in(
    const float* __restrict__ q, const float* __restrict__ k, const float* __restrict__ v)
{
    const int z = blockIdx.y;
    const float* src = (z == 0) ? q : (z == 1) ? k : v;
    __half* dst = g_a16[z];
    const size_t i = (size_t)blockIdx.x * 512 + threadIdx.x;   // float4 index
    float4 a = ((const float4*)src)[i];
    *(__half2*)&dst[i * 4]     = __floats2half2_rn(a.x, a.y);
    *(__half2*)&dst[i * 4 + 2] = __floats2half2_rn(a.z, a.w);
}

// ---------------------------------------------------------------------------
// Weight transpose + convert: g_wt16[z][n][k] = W_z[k][n] fp16
// ---------------------------------------------------------------------------
__global__ __launch_bounds__(256) void cvt_w(
    const float* __restrict__ Wq, const float* __restrict__ Wk,
    const float* __restrict__ Wv, const float* __restrict__ Wo)
{
    __shared__ float t[32][33];
    const int z = blockIdx.z;
    const float* W = (z == 0) ? Wq : (z == 1) ? Wk : (z == 2) ? Wv : Wo;
    __half* dst = g_wt16[z];
    const int tx = threadIdx.x & 31, ty = threadIdx.x >> 5;
    const int kb = blockIdx.y * 32, nb = blockIdx.x * 32;
#pragma unroll
    for (int i = 0; i < 4; ++i)
        t[ty + i * 8][tx] = W[(size_t)(kb + ty + i * 8) * Uu + nb + tx];
    __syncthreads();
#pragma unroll
    for (int i = 0; i < 4; ++i)
        dst[(size_t)(nb + ty + i * 8) * Uu + kb + tx] = __float2half_rn(t[tx][ty + i * 8]);
}

// ---------------------------------------------------------------------------
// FP16 QKV projection GEMM (r13/r15 winner, unchanged).
// ---------------------------------------------------------------------------
struct ProjSmem {
    uint32_t As[3][128][20];   // 30720 B  [r][k-pair]
    uint32_t Bs[3][128][20];   // 30720 B  [n][k-pair]
};

__global__ __launch_bounds__(256, 2) void proj_gemm(
    const float* __restrict__ bq, const float* __restrict__ bk, const float* __restrict__ bv)
{
    extern __shared__ __align__(1024) char smem_raw[];
    ProjSmem& sm = *reinterpret_cast<ProjSmem*>(smem_raw);

    const int z = blockIdx.z;
    const __half* A  = g_a16[z];
    const __half* Wt = g_wt16[z];
    const float* bias = (z == 0) ? bq : (z == 1) ? bk : bv;

    const int tid  = threadIdx.x;
    const int lane = tid & 31;
    const int wid  = tid >> 5;
    const int wm   = wid >> 2;            // 0..1
    const int wn   = wid & 3;             // 0..3
    const int kq   = lane & 3;
    const int ng   = lane >> 2;
    const int rowBase = blockIdx.y * 128;
    const int nBase   = blockIdx.x * 128;

    const uint32_t aS = smem_u32(&sm.As[0][0][0]);
    const uint32_t bS = smem_u32(&sm.Bs[0][0][0]);

    auto issue = [&](int s, int kt) {
        const int kb = kt * 32;
#pragma unroll
        for (int ii = 0; ii < 2; ++ii) {
            const int idx = tid + ii * 256;
            const int r = idx >> 2, c4 = idx & 3;
            cp16(aS + (((s * 128 + r) * 20 + c4 * 4) << 2),
                 &A[(size_t)(rowBase + r) * Uu + kb + c4 * 8]);
        }
#pragma unroll
        for (int ii = 0; ii < 2; ++ii) {
            const int idx = tid + ii * 256;
            const int n = idx >> 2, c4 = idx & 3;
            cp16(bS + (((s * 128 + n) * 20 + c4 * 4) << 2),
                 &Wt[(size_t)(nBase + n) * Uu + kb + c4 * 8]);
        }
        asm volatile("cp.async.commit_group;");
    };

    constexpr int NIT = Uu / 32;   // 16
    issue(0, 0);
    issue(1, 1);

    const int r0 = wm * 64 + ng;
    const int n0 = wn * 32 + ng;

    float c[4][4][4] = {};

    for (int kb = 0; kb < NIT; ++kb) {
        const int cur = kb % 3;
        if (kb + 1 < NIT) asm volatile("cp.async.wait_group 1;");
        else              asm volatile("cp.async.wait_group 0;");
        __syncthreads();

#pragma unroll
        for (int ks = 0; ks < 2; ++ks) {
            const int j0 = ks * 8 + kq;
            uint32_t a[4][4];
#pragma unroll
            for (int mt = 0; mt < 4; ++mt) {
                const int rr = r0 + mt * 16;
                a[mt][0] = sm.As[cur][rr][j0];
                a[mt][1] = sm.As[cur][rr + 8][j0];
                a[mt][2] = sm.As[cur][rr][j0 + 4];
                a[mt][3] = sm.As[cur][rr + 8][j0 + 4];
            }
#pragma unroll
            for (int nt = 0; nt < 4; ++nt) {
                uint32_t b[2];
                b[0] = sm.Bs[cur][n0 + nt * 8][j0];
                b[1] = sm.Bs[cur][n0 + nt * 8][j0 + 4];
#pragma unroll
                for (int mt = 0; mt < 4; ++mt)
                    mma_f16(c[mt][nt], a[mt], b);
            }
        }

        if (kb + 2 < NIT) issue((kb + 2) % 3, kb + 2);
    }

    const float scale = (z == 0) ? 0.125f : 1.0f;
#pragma unroll
    for (int mt = 0; mt < 4; ++mt) {
        const int rbase = rowBase + wm * 64 + mt * 16 + ng;
#pragma unroll
        for (int nt = 0; nt < 4; ++nt) {
            const int n = nBase + wn * 32 + nt * 8 + 2 * kq;
            const float2 bi = *(const float2*)&bias[n];
            const int hh = n >> 6, d = n & 63;
#pragma unroll
            for (int half_ = 0; half_ < 2; ++half_) {
                const int m = rbase + half_ * 8;
                const int bidx = m >> 10, t = m & 1023;
                float ox = fmaxf(c[mt][nt][half_ * 2 + 0] + bi.x, 0.f) * scale;
                float oy = fmaxf(c[mt][nt][half_ * 2 + 1] + bi.y, 0.f) * scale;
                if (z < 2) {
                    __half* dst = (z == 0) ? g_qh16 : g_kh16;
                    *(__half2*)&dst[((size_t)(hh * 8 + bidx) * Tt + t) * DH + d] =
                        __floats2half2_rn(ox, oy);
                } else {
                    g_vt16[((size_t)(hh * 8 + bidx) * DH + d) * Tt + t]     = __float2half_rn(ox);
                    g_vt16[((size_t)(hh * 8 + bidx) * DH + d + 1) * Tt + t] = __float2half_rn(oy);
                }
            }
        }
    }
}

// ---------------------------------------------------------------------------
// FP16 flash attention v3: occupancy-tuned.
//  - double-buffered K/V (L2-resident; depth-1 prefetch suffices)
//  - __launch_bounds__(128, 3): 3 CTAs/SM (12 warps) for latency hiding
//  - Q fragments hoisted; P register-direct (r15 winners)
// smem = 59152 B -> 3 CTAs fit (177 KB).
// ---------------------------------------------------------------------------
struct AttnSmem {
    uint32_t K[2][64][36];   // 18432 B [c][d-pair]
    uint32_t V[2][64][36];   // 18432 B V^T: [d][c-pair]
    uint32_t Q[64][36];      //  9216 B (prologue only after frag hoist)
    float pk[17][68];        //  4624 B (pek in prologue, pev in epilogue)
    float qrel[64][17];
    float wsum[64][16];
};

__global__ __launch_bounds__(128, 3) void attn_kernel(
    const float* __restrict__ pe_k, const float* __restrict__ pe_v)
{
    extern __shared__ __align__(1024) char smem_raw[];
    AttnSmem& s = *reinterpret_cast<AttnSmem*>(smem_raw);

    const int tid  = threadIdx.x;
    const int lane = tid & 31;
    const int w    = tid >> 5;
    const int kq   = lane & 3;
    const int ng   = lane >> 2;
    const int it   = 15 - (int)blockIdx.x;
    const int hb   = blockIdx.y;
    const int hh = hb >> 3, bidx = hb & 7;

    const __half* qbase = g_qh16 + (size_t)hb * Tt * DH;
    const __half* kbase = g_kh16 + (size_t)hb * Tt * DH;
    const __half* vbase = g_vt16 + (size_t)hb * DH * Tt;

    const uint32_t kS = smem_u32(&s.K[0][0][0]);
    const uint32_t vS = smem_u32(&s.V[0][0][0]);
    const uint32_t qS = smem_u32(&s.Q[0][0]);

    auto issue_tile = [&](int buf, int jt) {
#pragma unroll
        for (int ii = 0; ii < 4; ++ii) {
            const int i = tid + ii * 128;
            const int r = i >> 3, c8 = i & 7;
            cp16(kS + (((buf * 64 + r) * 36 + c8 * 4) << 2),
                 &kbase[(size_t)(jt * 64 + r) * DH + c8 * 8]);
        }
#pragma unroll
        for (int ii = 0; ii < 4; ++ii) {
            const int i = tid + ii * 128;
            const int d = i >> 3, c8 = i & 7;
            cp16(vS + (((buf * 64 + d) * 36 + c8 * 4) << 2),
                 &vbase[(size_t)d * Tt + jt * 64 + c8 * 8]);
        }
        asm volatile("cp.async.commit_group;");
    };

    // Prologue: tile0 + Q
    issue_tile(0, 0);
#pragma unroll
    for (int ii = 0; ii < 4; ++ii) {
        const int i = tid + ii * 128;
        const int r = i >> 3, c8 = i & 7;
        cp16(qS + ((r * 36 + c8 * 4) << 2),
             &qbase[(size_t)(it * 64 + r) * DH + c8 * 8]);
    }
    asm volatile("cp.async.commit_group;");

    for (int i = tid; i < 17 * 16; i += 128) {
        int m = i / 16, dq = i % 16;
        *(float4*)&s.pk[m][dq * 4] = *(const float4*)&pe_k[m * DH + dq * 4];
    }
    for (int i = tid; i < 1024; i += 128)
        (&s.wsum[0][0])[i] = 0.f;

    asm volatile("cp.async.wait_group 0;");
    __syncthreads();

    // qrel[r][m] = Qscaled . pe_k[m]
    for (int i = tid; i < 64 * 17; i += 128) {
        int r = i / 17, m = i % 17;
        float acc = 0.f;
#pragma unroll
        for (int j = 0; j < 32; ++j) {
            float2 f = __half22float2(*(const __half2*)&s.Q[r][j]);
            acc = fmaf(f.x, s.pk[m][2 * j], acc);
            acc = fmaf(f.y, s.pk[m][2 * j + 1], acc);
        }
        s.qrel[r][m] = acc;
    }
    __syncthreads();

    const int rl0 = w * 16 + ng;
    const float qrel0_0 = s.qrel[rl0][0];
    const float qrel0_1 = s.qrel[rl0 + 8][0];

    // Hoist Q fragments (loop-invariant)
    uint32_t qa[4][4];
#pragma unroll
    for (int ks = 0; ks < 4; ++ks) {
        const int j0 = ks * 8 + kq;
        qa[ks][0] = s.Q[rl0][j0];
        qa[ks][1] = s.Q[rl0 + 8][j0];
        qa[ks][2] = s.Q[rl0][j0 + 4];
        qa[ks][3] = s.Q[rl0 + 8][j0 + 4];
    }

    float o[8][4] = {};
    float mrow[2] = {-1e30f, -1e30f};
    float lrow[2] = {};

    for (int jt = 0; jt <= it; ++jt) {
        const int cur = jt & 1;
        // tile jt complete; barrier also ensures all warps done with jt-1
        asm volatile("cp.async.wait_group 0;");
        __syncthreads();
        // prefetch jt+1 into cur^1 (last read at iter jt-1)
        if (jt < it) issue_tile(cur ^ 1, jt + 1);

        // ---- S = Qs @ K^T ----
        float sc[8][4] = {};
#pragma unroll
        for (int ks = 0; ks < 4; ++ks) {
            const int j0 = ks * 8 + kq;
#pragma unroll
            for (int nt = 0; nt < 8; ++nt) {
                uint32_t b[2];
                b[0] = s.K[cur][nt * 8 + ng][j0];
                b[1] = s.K[cur][nt * 8 + ng][j0 + 4];
                mma_f16(sc[nt], qa[ks], b);
            }
        }

        const bool near = (jt >= it - 1);
        if (near) {
#pragma unroll
            for (int nt = 0; nt < 8; ++nt) {
#pragma unroll
                for (int ci = 0; ci < 4; ++ci) {
                    const int row_l = rl0 + ((ci >> 1) << 3);
                    const int tg = it * 64 + row_l;
                    const int sg = jt * 64 + nt * 8 + 2 * kq + (ci & 1);
                    const int delta = sg - tg;
                    if (delta > 0) sc[nt][ci] = -1e30f;
                    else {
                        int mi = delta + 16; if (mi < 0) mi = 0;
                        sc[nt][ci] += s.qrel[row_l][mi];
                    }
                }
            }
        } else {
#pragma unroll
            for (int nt = 0; nt < 8; ++nt) {
                sc[nt][0] += qrel0_0;
                sc[nt][1] += qrel0_0;
                sc[nt][2] += qrel0_1;
                sc[nt][3] += qrel0_1;
            }
        }

        // ---- online softmax ----
        float mt0 = -1e30f, mt1 = -1e30f;
#pragma unroll
        for (int nt = 0; nt < 8; ++nt) {
            mt0 = fmaxf(mt0, fmaxf(sc[nt][0], sc[nt][1]));
            mt1 = fmaxf(mt1, fmaxf(sc[nt][2], sc[nt][3]));
        }
        mt0 = fmaxf(mt0, __shfl_xor_sync(0xffffffffu, mt0, 1));
        mt0 = fmaxf(mt0, __shfl_xor_sync(0xffffffffu, mt0, 2));
        mt1 = fmaxf(mt1, __shfl_xor_sync(0xffffffffu, mt1, 1));
        mt1 = fmaxf(mt1, __shfl_xor_sync(0xffffffffu, mt1, 2));

        const float mnew0 = fmaxf(mrow[0], mt0);
        const float mnew1 = fmaxf(mrow[1], mt1);
        const float alpha0 = __expf(mrow[0] - mnew0);
        const float alpha1 = __expf(mrow[1] - mnew1);
        mrow[0] = mnew0; mrow[1] = mnew1;

#pragma unroll
        for (int nt = 0; nt < 8; ++nt) {
            sc[nt][0] = __expf(sc[nt][0] - mnew0);
            sc[nt][1] = __expf(sc[nt][1] - mnew0);
            sc[nt][2] = __expf(sc[nt][2] - mnew1);
            sc[nt][3] = __expf(sc[nt][3] - mnew1);
        }

        // ---- P fragments direct in registers (no smem) ----
        uint32_t pa[4][4];
#pragma unroll
        for (int j = 0; j < 4; ++j) {
            pa[j][0] = packh2(sc[2 * j][0],     sc[2 * j][1]);
            pa[j][1] = packh2(sc[2 * j][2],     sc[2 * j][3]);
            pa[j][2] = packh2(sc[2 * j + 1][0], sc[2 * j + 1][1]);
            pa[j][3] = packh2(sc[2 * j + 1][2], sc[2 * j + 1][3]);
        }

        float ps0 = 0.f, ps1 = 0.f;
#pragma unroll
        for (int nt = 0; nt < 8; ++nt) {
            ps0 += sc[nt][0] + sc[nt][1];
            ps1 += sc[nt][2] + sc[nt][3];
        }
        ps0 += __shfl_xor_sync(0xffffffffu, ps0, 1);
        ps0 += __shfl_xor_sync(0xffffffffu, ps0, 2);
        ps1 += __shfl_xor_sync(0xffffffffu, ps1, 1);
        ps1 += __shfl_xor_sync(0xffffffffu, ps1, 2);
        lrow[0] = lrow[0] * alpha0 + ps0;
        lrow[1] = lrow[1] * alpha1 + ps1;

#pragma unroll
        for (int nt = 0; nt < 8; ++nt) {
            o[nt][0] *= alpha0; o[nt][1] *= alpha0;
            o[nt][2] *= alpha1; o[nt][3] *= alpha1;
        }

        // ---- wsum bookkeeping ----
#pragma unroll
        for (int j = 0; j < 4; ++j) {
            s.wsum[rl0][kq * 4 + j]     *= alpha0;
            s.wsum[rl0 + 8][kq * 4 + j] *= alpha1;
        }
        __syncwarp();
        if (near) {
#pragma unroll
            for (int nt = 0; nt < 8; ++nt) {
#pragma unroll
                for (int ci = 0; ci < 4; ++ci) {
                    const int row_l = rl0 + ((ci >> 1) << 3);
                    const int delta = (jt * 64 + nt * 8 + 2 * kq + (ci & 1)) - (it * 64 + row_l);
                    if (delta >= -15 && delta <= 0)
                        s.wsum[row_l][delta + 15] += sc[nt][ci];
                }
            }
        }
        __syncwarp();

        // ---- O += P @ V ----
#pragma unroll
        for (int ks = 0; ks < 4; ++ks) {
            const int j0 = ks * 8 + kq;
#pragma unroll
            for (int nt = 0; nt < 8; ++nt) {
                uint32_t b[2];
                b[0] = s.V[cur][nt * 8 + ng][j0];
                b[1] = s.V[cur][nt * 8 + ng][j0 + 4];
                mma_f16(o[nt], pa[ks], b);
            }
        }
    }

    __syncthreads();
    for (int i = tid; i < 17 * 16; i += 128) {
        int m = i / 16, dq = i % 16;
        *(float4*)&s.pk[m][dq * 4] = *(const float4*)&pe_v[m * DH + dq * 4];
    }
    __syncthreads();

#pragma unroll
    for (int half_ = 0; half_ < 2; ++half_) {
        const int rl = rl0 + 8 * half_;
        const int tg = it * 64 + rl;
        const float l = lrow[half_];
        float wm[16], sumw = 0.f;
#pragma unroll
        for (int m = 0; m < 16; ++m) { wm[m] = s.wsum[rl][m]; sumw += wm[m]; }
        const float w0 = l - sumw;
        const float inv = 1.f / l;
#pragma unroll
        for (int nt = 0; nt < 8; ++nt) {
            const int d0 = nt * 8 + 2 * kq;
            float acc0 = o[nt][half_ * 2 + 0] + w0 * s.pk[0][d0];
            float acc1 = o[nt][half_ * 2 + 1] + w0 * s.pk[0][d0 + 1];
#pragma unroll
            for (int m = 1; m <= 16; ++m) {
                acc0 = fmaf(wm[m - 1], s.pk[m][d0], acc0);
                acc1 = fmaf(wm[m - 1], s.pk[m][d0 + 1], acc1);
            }
            *(__half2*)&g_att16[((size_t)(bidx * Tt) + tg) * Uu + hh * DH + d0] =
                __floats2half2_rn(acc0 * inv, acc1 * inv);
        }
    }
}

// ---------------------------------------------------------------------------
// Fused out-projection + residual + LayerNorm (r13/r15 winner, unchanged).
// ---------------------------------------------------------------------------
struct OProjSmem {
    uint32_t As[4][64][12];     // 12288 B [r][k-pair]
    uint32_t Bs[4][512][12];    // 98304 B [n][k-pair]
    float part[2][8][64];       // 4096 B
    float mu[64];
    float rs[64];
};

__global__ __launch_bounds__(256) void oproj_ln(
    const float* __restrict__ bo,
    const float* __restrict__ res,
    const float* __restrict__ gamma, const float* __restrict__ beta,
    float* __restrict__ out)
{
    extern __shared__ __align__(1024) char smem_raw[];
    OProjSmem& sm = *reinterpret_cast<OProjSmem*>(smem_raw);

    const int tid  = threadIdx.x;
    const int lane = tid & 31;
    const int w    = tid >> 5;
    const int kq   = lane & 3;
    const int ng   = lane >> 2;
    const int rowBase = blockIdx.x * 64;

    const __half* Wt = g_wt16[3];
    const uint32_t aS = smem_u32(&sm.As[0][0][0]);
    const uint32_t bS = smem_u32(&sm.Bs[0][0][0]);

    auto issue = [&](int s, int kt) {
        const int kb = kt * 16;
        if (tid < 128) {
            const int r = tid >> 1, c2 = tid & 1;
            cp16(aS + (((s * 64 + r) * 12 + c2 * 4) << 2),
                 &g_att16[(size_t)(rowBase + r) * Uu + kb + c2 * 8]);
        }
#pragma unroll
        for (int ii = 0; ii < 4; ++ii) {
            const int idx = tid + ii * 256;
            const int n = idx >> 1, c2 = idx & 1;
            cp16(bS + (((s * 512 + n) * 12 + c2 * 4) << 2),
                 &Wt[(size_t)n * Uu + kb + c2 * 8]);
        }
        asm volatile("cp.async.commit_group;");
    };

    constexpr int NIT = Uu / 16;   // 32
    issue(0, 0);
    issue(1, 1);
    issue(2, 2);

    float c[4][8][4] = {};

    for (int kb = 0; kb < NIT; ++kb) {
        const int cur = kb & 3;
        if      (kb + 2 < NIT) asm volatile("cp.async.wait_group 2;");
        else if (kb + 1 < NIT) asm volatile("cp.async.wait_group 1;");
        else                   asm volatile("cp.async.wait_group 0;");
        __syncthreads();

        uint32_t a[4][4];
#pragma unroll
        for (int mt = 0; mt < 4; ++mt) {
            const int r0 = mt * 16 + ng;
            a[mt][0] = sm.As[cur][r0][kq];
            a[mt][1] = sm.As[cur][r0 + 8][kq];
            a[mt][2] = sm.As[cur][r0][kq + 4];
            a[mt][3] = sm.As[cur][r0 + 8][kq + 4];
        }
#pragma unroll
        for (int nt = 0; nt < 8; ++nt) {
            uint32_t b[2];
            const int n0 = w * 64 + nt * 8 + ng;
            b[0] = sm.Bs[cur][n0][kq];
            b[1] = sm.Bs[cur][n0][kq + 4];
#pragma unroll
            for (int mt = 0; mt < 4; ++mt)
                mma_f16(c[mt][nt], a[mt], b);
        }

        if (kb + 3 < NIT) issue((kb + 3) & 3, kb + 3);
    }

    float psum[8] = {}, psq[8] = {};
#pragma unroll
    for (int mt = 0; mt < 4; ++mt) {
#pragma unroll
        for (int half_ = 0; half_ < 2; ++half_) {
            const int m = rowBase + mt * 16 + ng + half_ * 8;
            const int slot = mt * 2 + half_;
#pragma unroll
            for (int nt = 0; nt < 8; ++nt) {
                const int n = w * 64 + nt * 8 + 2 * kq;
                const float2 bi = *(const float2*)&bo[n];
                const float2 r2 = *(const float2*)&res[(size_t)m * Uu + n];
                float vx = fmaxf(c[mt][nt][half_ * 2 + 0] + bi.x, 0.f) + r2.x;
                float vy = fmaxf(c[mt][nt][half_ * 2 + 1] + bi.y, 0.f) + r2.y;
                c[mt][nt][half_ * 2 + 0] = vx;
                c[mt][nt][half_ * 2 + 1] = vy;
                psum[slot] += vx + vy;
                psq[slot]  += vx * vx + vy * vy;
            }
        }
    }
#pragma unroll
    for (int slot = 0; slot < 8; ++slot) {
        psum[slot] += __shfl_xor_sync(0xffffffffu, psum[slot], 1);
        psum[slot] += __shfl_xor_sync(0xffffffffu, psum[slot], 2);
        psq[slot]  += __shfl_xor_sync(0xffffffffu, psq[slot], 1);
        psq[slot]  += __shfl_xor_sync(0xffffffffu, psq[slot], 2);
    }
    if (kq == 0) {
#pragma unroll
        for (int mt = 0; mt < 4; ++mt)
#pragma unroll
            for (int half_ = 0; half_ < 2; ++half_) {
                const int rl = mt * 16 + ng + half_ * 8;
                sm.part[0][w][rl] = psum[mt * 2 + half_];
                sm.part[1][w][rl] = psq[mt * 2 + half_];
            }
    }
    __syncthreads();

    if (tid < 64) {
        float su = 0.f, sq = 0.f;
#pragma unroll
        for (int wi = 0; wi < 8; ++wi) {
            su += sm.part[0][wi][tid];
            sq += sm.part[1][wi][tid];
        }
        const float mu = su * (1.f / Uu);
        const float var = sq * (1.f / Uu) - mu * mu;
        sm.mu[tid] = mu;
        sm.rs[tid] = rsqrtf(var + 1e-3f);
    }
    __syncthreads();

#pragma unroll
    for (int mt = 0; mt < 4; ++mt) {
#pragma unroll
        for (int half_ = 0; half_ < 2; ++half_) {
            const int rl = mt * 16 + ng + half_ * 8;
            const int m = rowBase + rl;
            const float mu = sm.mu[rl];
            const float rstd = sm.rs[rl];
#pragma unroll
            for (int nt = 0; nt < 8; ++nt) {
                const int n = w * 64 + nt * 8 + 2 * kq;
                const float2 g2 = *(const float2*)&gamma[n];
                const float2 b2 = *(const float2*)&beta[n];
                float2 o;
                o.x = (c[mt][nt][half_ * 2 + 0] - mu) * rstd * g2.x + b2.x;
                o.y = (c[mt][nt][half_ * 2 + 1] - mu) * rstd * g2.y + b2.y;
                *(float2*)&out[(size_t)m * Uu + n] = o;
            }
        }
    }
}

// ---------------------------------------------------------------------------
extern "C" void kernel_launch(void* const* d_in, const int* in_sizes, int n_in,
                              void* d_out, int out_size) {
    (void)n_in; (void)out_size;

    int iq, ik, iv, iWq, ibq, iWk, ibk, iWv, ibv, iWo, ibo, ig, ibe, ipk, ipv;
    if (in_sizes[0] == Bb * Tt * Uu) {
        iq = 0; ik = 1; iv = 2; iWq = 3; ibq = 4; iWk = 5; ibk = 6;
        iWv = 7; ibv = 8; iWo = 9; ibo = 10; ig = 11; ibe = 12; ipk = 13; ipv = 14;
    } else if (in_sizes[0] == Uu * Uu) {
        iWk = 0; iWo = 1; iWq = 2; iWv = 3; ibe = 4; ibk = 5; ibo = 6;
        ibq = 7; ibv = 8; ig = 9; ik = 10; ipk = 11; ipv = 12; iq = 13; iv = 14;
    } else {
        ibe = 0; ibk = 1; ibo = 2; ibq = 3; ibv = 4; ig = 5; ik = 6;
        ipk = 7; ipv = 8; iq = 9; iv = 10; iWk = 11; iWo = 12; iWq = 13; iWv = 14;
    }

    const float* q    = (const float*)d_in[iq];
    const float* k    = (const float*)d_in[ik];
    const float* v    = (const float*)d_in[iv];
    const float* Wq   = (const float*)d_in[iWq];
    const float* bq   = (const float*)d_in[ibq];
    const float* Wk   = (const float*)d_in[iWk];
    const float* bk   = (const float*)d_in[ibk];
    const float* Wv   = (const float*)d_in[iWv];
    const float* bv   = (const float*)d_in[ibv];
    const float* Wo   = (const float*)d_in[iWo];
    const float* bo   = (const float*)d_in[ibo];
    const float* gamma= (const float*)d_in[ig];
    const float* beta = (const float*)d_in[ibe];
    const float* pek  = (const float*)d_in[ipk];
    const float* pev  = (const float*)d_in[ipv];
    float* out = (float*)d_out;

    cudaFuncSetAttribute(attn_kernel, cudaFuncAttributeMaxDynamicSharedMemorySize,
                         (int)sizeof(AttnSmem));
    cudaFuncSetAttribute(proj_gemm, cudaFuncAttributeMaxDynamicSharedMemorySize,
                         (int)sizeof(ProjSmem));
    cudaFuncSetAttribute(oproj_ln, cudaFuncAttributeMaxDynamicSharedMemorySize,
                         (int)sizeof(OProjSmem));

    // Convert inputs + weights to fp16 (weights transposed)
    cvt_in<<<dim3(MR * Uu / 4 / 512, 3), 512>>>(q, k, v);
    cvt_w<<<dim3(16, 16, 4), 256>>>(Wq, Wk, Wv, Wo);

    // Q/K/V projections (fp16 mma), head-split fp16 outputs
    proj_gemm<<<dim3(4, 64, 3), 256, sizeof(ProjSmem)>>>(bq, bk, bv);

    attn_kernel<<<dim3(16, 64), 128, sizeof(AttnSmem)>>>(pek, pev);

    // Fused output projection + residual + LayerNorm -> final fp32 output
    oproj_ln<<<128, 256, sizeof(OProjSmem)>>>(bo, q, gamma, beta, out);
}

// round 17
// speedup vs baseline: 1.0154x; 1.0154x over previous
#include <cuda_runtime.h>
#include <cuda_fp16.h>
#include <math.h>
#include <stdint.h>

// Problem constants
static constexpr int Bb  = 8;
static constexpr int Tt  = 1024;
static constexpr int Uu  = 512;
static constexpr int DH  = 64;
static constexpr int HB  = 64;           // H*B
static constexpr int MR  = Bb * Tt;      // 8192 rows

// Scratch (device globals)
__device__ __half g_a16[3][(size_t)MR * Uu];     // q,k,v inputs fp16
__device__ __half g_wt16[4][(size_t)Uu * Uu];    // W^T (n-major, k contiguous) fp16
__device__ __half g_qh16[(size_t)HB * Tt * DH];  // head-split, pre-scaled 1/8
__device__ __half g_kh16[(size_t)HB * Tt * DH];  // head-split [hb][t][d]
__device__ __half g_vt16[(size_t)HB * DH * Tt];  // head-split TRANSPOSED [hb][d][t]
__device__ __half g_att16[(size_t)MR * Uu];      // attention out, merged

// ---------------------------------------------------------------------------
// Helpers
// ---------------------------------------------------------------------------
__device__ __forceinline__ void mma_f16(float c[4], const uint32_t a[4], const uint32_t b[2]) {
    asm volatile(
        "mma.sync.aligned.m16n8k16.row.col.f32.f16.f16.f32 "
        "{%0,%1,%2,%3}, {%4,%5,%6,%7}, {%8,%9}, {%0,%1,%2,%3};"
        : "+f"(c[0]), "+f"(c[1]), "+f"(c[2]), "+f"(c[3])
        : "r"(a[0]), "r"(a[1]), "r"(a[2]), "r"(a[3]), "r"(b[0]), "r"(b[1]));
}

__device__ __forceinline__ void cp16(uint32_t saddr, const void* gptr) {
    asm volatile("cp.async.cg.shared.global [%0], [%1], 16;" :: "r"(saddr), "l"(gptr));
}

__device__ __forceinline__ uint32_t smem_u32(const void* p) {
    uint32_t a;
    asm("{ .reg .u64 t; cvta.to.shared.u64 t, %1; cvt.u32.u64 %0, t; }" : "=r"(a) : "l"(p));
    return a;
}

// pack two fp32 -> f16x2 in a b32 register (RN rounding)
__device__ __forceinline__ uint32_t packh2(float x, float y) {
    uint32_t r;
    asm("cvt.rn.f16x2.f32 %0, %1, %2;" : "=r"(r) : "f"(y), "f"(x));
    return r;
}

// ldmatrix x4: 4 8x8 f16 matrices; threads 0-7/8-15/16-23/24-31 supply rows
__device__ __forceinline__ void ldsm_x4(
    uint32_t& r0, uint32_t& r1, uint32_t& r2, uint32_t& r3, uint32_t addr)
{
    asm volatile("ldmatrix.sync.aligned.m8n8.x4.shared.b16 {%0,%1,%2,%3}, [%4];"
                 : "=r"(r0), "=r"(r1), "=r"(r2), "=r"(r3) : "r"(addr));
}

// ---------------------------------------------------------------------------
// Input conversion: q/k/v fp32 -> fp16 (grid.y = z)
// ---------------------------------------------------------------------------
__global__ __launch_bounds__(512) void cvt_in(
    const float* __restrict__ q, const float* __restrict__ k, const float* __restrict__ v)
{
    const int z = blockIdx.y;
    const float* src = (z == 0) ? q : (z == 1) ? k : v;
    __half* dst = g_a16[z];
    const size_t i = (size_t)blockIdx.x * 512 + threadIdx.x;   // float4 index
    float4 a = ((const float4*)src)[i];
    *(__half2*)&dst[i * 4]     = __floats2half2_rn(a.x, a.y);
    *(__half2*)&dst[i * 4 + 2] = __floats2half2_rn(a.z, a.w);
}

// ---------------------------------------------------------------------------
// Weight transpose + convert: g_wt16[z][n][k] = W_z[k][n] fp16
// ---------------------------------------------------------------------------
__global__ __launch_bounds__(256) void cvt_w(
    const float* __restrict__ Wq, const float* __restrict__ Wk,
    const float* __restrict__ Wv, const float* __restrict__ Wo)
{
    __shared__ float t[32][33];
    const int z = blockIdx.z;
    const float* W = (z == 0) ? Wq : (z == 1) ? Wk : (z == 2) ? Wv : Wo;
    __half* dst = g_wt16[z];
    const int tx = threadIdx.x & 31, ty = threadIdx.x >> 5;
    const int kb = blockIdx.y * 32, nb = blockIdx.x * 32;
#pragma unroll
    for (int i = 0; i < 4; ++i)
        t[ty + i * 8][tx] = W[(size_t)(kb + ty + i * 8) * Uu + nb + tx];
    __syncthreads();
#pragma unroll
    for (int i = 0; i < 4; ++i)
        dst[(size_t)(nb + ty + i * 8) * Uu + kb + tx] = __float2half_rn(t[tx][ty + i * 8]);
}

// ---------------------------------------------------------------------------
// FP16 QKV projection GEMM (r13/r15 winner, unchanged).
// ---------------------------------------------------------------------------
struct ProjSmem {
    uint32_t As[3][128][20];   // 30720 B  [r][k-pair]
    uint32_t Bs[3][128][20];   // 30720 B  [n][k-pair]
};

__global__ __launch_bounds__(256, 2) void proj_gemm(
    const float* __restrict__ bq, const float* __restrict__ bk, const float* __restrict__ bv)
{
    extern __shared__ __align__(1024) char smem_raw[];
    ProjSmem& sm = *reinterpret_cast<ProjSmem*>(smem_raw);

    const int z = blockIdx.z;
    const __half* A  = g_a16[z];
    const __half* Wt = g_wt16[z];
    const float* bias = (z == 0) ? bq : (z == 1) ? bk : bv;

    const int tid  = threadIdx.x;
    const int lane = tid & 31;
    const int wid  = tid >> 5;
    const int wm   = wid >> 2;            // 0..1
    const int wn   = wid & 3;             // 0..3
    const int kq   = lane & 3;
    const int ng   = lane >> 2;
    const int rowBase = blockIdx.y * 128;
    const int nBase   = blockIdx.x * 128;

    const uint32_t aS = smem_u32(&sm.As[0][0][0]);
    const uint32_t bS = smem_u32(&sm.Bs[0][0][0]);

    auto issue = [&](int s, int kt) {
        const int kb = kt * 32;
#pragma unroll
        for (int ii = 0; ii < 2; ++ii) {
            const int idx = tid + ii * 256;
            const int r = idx >> 2, c4 = idx & 3;
            cp16(aS + (((s * 128 + r) * 20 + c4 * 4) << 2),
                 &A[(size_t)(rowBase + r) * Uu + kb + c4 * 8]);
        }
#pragma unroll
        for (int ii = 0; ii < 2; ++ii) {
            const int idx = tid + ii * 256;
            const int n = idx >> 2, c4 = idx & 3;
            cp16(bS + (((s * 128 + n) * 20 + c4 * 4) << 2),
                 &Wt[(size_t)(nBase + n) * Uu + kb + c4 * 8]);
        }
        asm volatile("cp.async.commit_group;");
    };

    constexpr int NIT = Uu / 32;   // 16
    issue(0, 0);
    issue(1, 1);

    const int r0 = wm * 64 + ng;
    const int n0 = wn * 32 + ng;

    float c[4][4][4] = {};

    for (int kb = 0; kb < NIT; ++kb) {
        const int cur = kb % 3;
        if (kb + 1 < NIT) asm volatile("cp.async.wait_group 1;");
        else              asm volatile("cp.async.wait_group 0;");
        __syncthreads();

#pragma unroll
        for (int ks = 0; ks < 2; ++ks) {
            const int j0 = ks * 8 + kq;
            uint32_t a[4][4];
#pragma unroll
            for (int mt = 0; mt < 4; ++mt) {
                const int rr = r0 + mt * 16;
                a[mt][0] = sm.As[cur][rr][j0];
                a[mt][1] = sm.As[cur][rr + 8][j0];
                a[mt][2] = sm.As[cur][rr][j0 + 4];
                a[mt][3] = sm.As[cur][rr + 8][j0 + 4];
            }
#pragma unroll
            for (int nt = 0; nt < 4; ++nt) {
                uint32_t b[2];
                b[0] = sm.Bs[cur][n0 + nt * 8][j0];
                b[1] = sm.Bs[cur][n0 + nt * 8][j0 + 4];
#pragma unroll
                for (int mt = 0; mt < 4; ++mt)
                    mma_f16(c[mt][nt], a[mt], b);
            }
        }

        if (kb + 2 < NIT) issue((kb + 2) % 3, kb + 2);
    }

    const float scale = (z == 0) ? 0.125f : 1.0f;
#pragma unroll
    for (int mt = 0; mt < 4; ++mt) {
        const int rbase = rowBase + wm * 64 + mt * 16 + ng;
#pragma unroll
        for (int nt = 0; nt < 4; ++nt) {
            const int n = nBase + wn * 32 + nt * 8 + 2 * kq;
            const float2 bi = *(const float2*)&bias[n];
            const int hh = n >> 6, d = n & 63;
#pragma unroll
            for (int half_ = 0; half_ < 2; ++half_) {
                const int m = rbase + half_ * 8;
                const int bidx = m >> 10, t = m & 1023;
                float ox = fmaxf(c[mt][nt][half_ * 2 + 0] + bi.x, 0.f) * scale;
                float oy = fmaxf(c[mt][nt][half_ * 2 + 1] + bi.y, 0.f) * scale;
                if (z < 2) {
                    __half* dst = (z == 0) ? g_qh16 : g_kh16;
                    *(__half2*)&dst[((size_t)(hh * 8 + bidx) * Tt + t) * DH + d] =
                        __floats2half2_rn(ox, oy);
                } else {
                    g_vt16[((size_t)(hh * 8 + bidx) * DH + d) * Tt + t]     = __float2half_rn(ox);
                    g_vt16[((size_t)(hh * 8 + bidx) * DH + d + 1) * Tt + t] = __float2half_rn(oy);
                }
            }
        }
    }
}

// ---------------------------------------------------------------------------
// FP16 flash attention v4 (r15 config + ldmatrix b-fragments):
//  - triple-buffered K/V, depth-2 prefetch (r15 winner)
//  - Q fragments hoisted; P register-direct
//  - K/V b-fragments via ldmatrix.x4: 32 LDSM replaces 128 LDS per tile/warp
// ---------------------------------------------------------------------------
struct AttnSmem {
    uint32_t K[3][64][36];   // 27648 B [c][d-pair]
    uint32_t V[3][64][36];   // 27648 B V^T: [d][c-pair]
    uint32_t Q[64][36];      //  9216 B (prologue only after frag hoist)
    float pk[17][68];        //  4624 B (pek in prologue, pev in epilogue)
    float qrel[64][17];
    float wsum[64][16];
};

__global__ __launch_bounds__(128) void attn_kernel(
    const float* __restrict__ pe_k, const float* __restrict__ pe_v)
{
    extern __shared__ __align__(1024) char smem_raw[];
    AttnSmem& s = *reinterpret_cast<AttnSmem*>(smem_raw);

    const int tid  = threadIdx.x;
    const int lane = tid & 31;
    const int w    = tid >> 5;
    const int kq   = lane & 3;
    const int ng   = lane >> 2;
    const int it   = 15 - (int)blockIdx.x;
    const int hb   = blockIdx.y;
    const int hh = hb >> 3, bidx = hb & 7;

    const __half* qbase = g_qh16 + (size_t)hb * Tt * DH;
    const __half* kbase = g_kh16 + (size_t)hb * Tt * DH;
    const __half* vbase = g_vt16 + (size_t)hb * DH * Tt;

    const uint32_t kS = smem_u32(&s.K[0][0][0]);
    const uint32_t vS = smem_u32(&s.V[0][0][0]);
    const uint32_t qS = smem_u32(&s.Q[0][0]);

    // ldmatrix per-thread row pointers: matrix id m = lane>>3, row r = lane&7
    //   matrices (ks, ntp): m0 = rows 16ntp..+7   pairs 8ks..+3
    //                       m1 = rows 16ntp..+7   pairs 8ks+4..+7
    //                       m2 = rows 16ntp+8..+15 pairs 8ks..+3
    //                       m3 = rows 16ntp+8..+15 pairs 8ks+4..+7
    const int mID = lane >> 3, rr8 = lane & 7;
    const uint32_t fragOff = (((uint32_t)(8 * (mID >> 1) + rr8) * 36 + 4 * (mID & 1)) << 2);
    const uint32_t kFragBase = kS + fragOff;
    const uint32_t vFragBase = vS + fragOff;

    auto issue_tile = [&](int buf, int jt) {
#pragma unroll
        for (int ii = 0; ii < 4; ++ii) {
            const int i = tid + ii * 128;
            const int r = i >> 3, c8 = i & 7;
            cp16(kS + (((buf * 64 + r) * 36 + c8 * 4) << 2),
                 &kbase[(size_t)(jt * 64 + r) * DH + c8 * 8]);
        }
#pragma unroll
        for (int ii = 0; ii < 4; ++ii) {
            const int i = tid + ii * 128;
            const int d = i >> 3, c8 = i & 7;
            cp16(vS + (((buf * 64 + d) * 36 + c8 * 4) << 2),
                 &vbase[(size_t)d * Tt + jt * 64 + c8 * 8]);
        }
        asm volatile("cp.async.commit_group;");
    };

    // Prologue: tile0, Q, tile1 (3 groups)
    issue_tile(0, 0);
#pragma unroll
    for (int ii = 0; ii < 4; ++ii) {
        const int i = tid + ii * 128;
        const int r = i >> 3, c8 = i & 7;
        cp16(qS + ((r * 36 + c8 * 4) << 2),
             &qbase[(size_t)(it * 64 + r) * DH + c8 * 8]);
    }
    asm volatile("cp.async.commit_group;");
    if (it >= 1) issue_tile(1, 1);

    for (int i = tid; i < 17 * 16; i += 128) {
        int m = i / 16, dq = i % 16;
        *(float4*)&s.pk[m][dq * 4] = *(const float4*)&pe_k[m * DH + dq * 4];
    }
    for (int i = tid; i < 1024; i += 128)
        (&s.wsum[0][0])[i] = 0.f;

    if (it >= 1) asm volatile("cp.async.wait_group 1;");  // tile0 + Q done
    else         asm volatile("cp.async.wait_group 0;");
    __syncthreads();

    // qrel[r][m] = Qscaled . pe_k[m]
    for (int i = tid; i < 64 * 17; i += 128) {
        int r = i / 17, m = i % 17;
        float acc = 0.f;
#pragma unroll
        for (int j = 0; j < 32; ++j) {
            float2 f = __half22float2(*(const __half2*)&s.Q[r][j]);
            acc = fmaf(f.x, s.pk[m][2 * j], acc);
            acc = fmaf(f.y, s.pk[m][2 * j + 1], acc);
        }
        s.qrel[r][m] = acc;
    }
    __syncthreads();

    const int rl0 = w * 16 + ng;
    const float qrel0_0 = s.qrel[rl0][0];
    const float qrel0_1 = s.qrel[rl0 + 8][0];

    // Hoist Q fragments (loop-invariant)
    uint32_t qa[4][4];
#pragma unroll
    for (int ks = 0; ks < 4; ++ks) {
        const int j0 = ks * 8 + kq;
        qa[ks][0] = s.Q[rl0][j0];
        qa[ks][1] = s.Q[rl0 + 8][j0];
        qa[ks][2] = s.Q[rl0][j0 + 4];
        qa[ks][3] = s.Q[rl0 + 8][j0 + 4];
    }

    float o[8][4] = {};
    float mrow[2] = {-1e30f, -1e30f};
    float lrow[2] = {};

    for (int jt = 0; jt <= it; ++jt) {
        const int cur = jt % 3;
        if (jt < it) asm volatile("cp.async.wait_group 1;");
        else         asm volatile("cp.async.wait_group 0;");
        __syncthreads();
        if (jt + 2 <= it) issue_tile((jt + 2) % 3, jt + 2);

        const uint32_t kT = kFragBase + ((uint32_t)(cur * 64 * 36) << 2);
        const uint32_t vT = vFragBase + ((uint32_t)(cur * 64 * 36) << 2);

        // ---- S = Qs @ K^T  (b-frags via ldmatrix.x4) ----
        float sc[8][4] = {};
#pragma unroll
        for (int ks = 0; ks < 4; ++ks) {
#pragma unroll
            for (int ntp = 0; ntp < 4; ++ntp) {
                uint32_t b0, b1, b2, b3;
                ldsm_x4(b0, b1, b2, b3,
                        kT + ((uint32_t)(ntp * 16 * 36 + ks * 8) << 2));
                uint32_t ba[2] = {b0, b1}, bb[2] = {b2, b3};
                mma_f16(sc[2 * ntp],     qa[ks], ba);
                mma_f16(sc[2 * ntp + 1], qa[ks], bb);
            }
        }

        const bool near = (jt >= it - 1);
        if (near) {
#pragma unroll
            for (int nt = 0; nt < 8; ++nt) {
#pragma unroll
                for (int ci = 0; ci < 4; ++ci) {
                    const int row_l = rl0 + ((ci >> 1) << 3);
                    const int tg = it * 64 + row_l;
                    const int sg = jt * 64 + nt * 8 + 2 * kq + (ci & 1);
                    const int delta = sg - tg;
                    if (delta > 0) sc[nt][ci] = -1e30f;
                    else {
                        int mi = delta + 16; if (mi < 0) mi = 0;
                        sc[nt][ci] += s.qrel[row_l][mi];
                    }
                }
            }
        } else {
#pragma unroll
            for (int nt = 0; nt < 8; ++nt) {
                sc[nt][0] += qrel0_0;
                sc[nt][1] += qrel0_0;
                sc[nt][2] += qrel0_1;
                sc[nt][3] += qrel0_1;
            }
        }

        // ---- online softmax ----
        float mt0 = -1e30f, mt1 = -1e30f;
#pragma unroll
        for (int nt = 0; nt < 8; ++nt) {
            mt0 = fmaxf(mt0, fmaxf(sc[nt][0], sc[nt][1]));
            mt1 = fmaxf(mt1, fmaxf(sc[nt][2], sc[nt][3]));
        }
        mt0 = fmaxf(mt0, __shfl_xor_sync(0xffffffffu, mt0, 1));
        mt0 = fmaxf(mt0, __shfl_xor_sync(0xffffffffu, mt0, 2));
        mt1 = fmaxf(mt1, __shfl_xor_sync(0xffffffffu, mt1, 1));
        mt1 = fmaxf(mt1, __shfl_xor_sync(0xffffffffu, mt1, 2));

        const float mnew0 = fmaxf(mrow[0], mt0);
        const float mnew1 = fmaxf(mrow[1], mt1);
        const float alpha0 = __expf(mrow[0] - mnew0);
        const float alpha1 = __expf(mrow[1] - mnew1);
        mrow[0] = mnew0; mrow[1] = mnew1;

#pragma unroll
        for (int nt = 0; nt < 8; ++nt) {
            sc[nt][0] = __expf(sc[nt][0] - mnew0);
            sc[nt][1] = __expf(sc[nt][1] - mnew0);
            sc[nt][2] = __expf(sc[nt][2] - mnew1);
            sc[nt][3] = __expf(sc[nt][3] - mnew1);
        }

        // ---- P fragments direct in registers (no smem) ----
        uint32_t pa[4][4];
#pragma unroll
        for (int j = 0; j < 4; ++j) {
            pa[j][0] = packh2(sc[2 * j][0],     sc[2 * j][1]);
            pa[j][1] = packh2(sc[2 * j][2],     sc[2 * j][3]);
            pa[j][2] = packh2(sc[2 * j + 1][0], sc[2 * j + 1][1]);
            pa[j][3] = packh2(sc[2 * j + 1][2], sc[2 * j + 1][3]);
        }

        float ps0 = 0.f, ps1 = 0.f;
#pragma unroll
        for (int nt = 0; nt < 8; ++nt) {
            ps0 += sc[nt][0] + sc[nt][1];
            ps1 += sc[nt][2] + sc[nt][3];
        }
        ps0 += __shfl_xor_sync(0xffffffffu, ps0, 1);
        ps0 += __shfl_xor_sync(0xffffffffu, ps0, 2);
        ps1 += __shfl_xor_sync(0xffffffffu, ps1, 1);
        ps1 += __shfl_xor_sync(0xffffffffu, ps1, 2);
        lrow[0] = lrow[0] * alpha0 + ps0;
        lrow[1] = lrow[1] * alpha1 + ps1;

#pragma unroll
        for (int nt = 0; nt < 8; ++nt) {
            o[nt][0] *= alpha0; o[nt][1] *= alpha0;
            o[nt][2] *= alpha1; o[nt][3] *= alpha1;
        }

        // ---- wsum bookkeeping ----
#pragma unroll
        for (int j = 0; j < 4; ++j) {
            s.wsum[rl0][kq * 4 + j]     *= alpha0;
            s.wsum[rl0 + 8][kq * 4 + j] *= alpha1;
        }
        __syncwarp();
        if (near) {
#pragma unroll
            for (int nt = 0; nt < 8; ++nt) {
#pragma unroll
                for (int ci = 0; ci < 4; ++ci) {
                    const int row_l = rl0 + ((ci >> 1) << 3);
                    const int delta = (jt * 64 + nt * 8 + 2 * kq + (ci & 1)) - (it * 64 + row_l);
                    if (delta >= -15 && delta <= 0)
                        s.wsum[row_l][delta + 15] += sc[nt][ci];
                }
            }
        }
        __syncwarp();

        // ---- O += P @ V  (b-frags via ldmatrix.x4) ----
#pragma unroll
        for (int ks = 0; ks < 4; ++ks) {
#pragma unroll
            for (int ntp = 0; ntp < 4; ++ntp) {
                uint32_t b0, b1, b2, b3;
                ldsm_x4(b0, b1, b2, b3,
                        vT + ((uint32_t)(ntp * 16 * 36 + ks * 8) << 2));
                uint32_t ba[2] = {b0, b1}, bb[2] = {b2, b3};
                mma_f16(o[2 * ntp],     pa[ks], ba);
                mma_f16(o[2 * ntp + 1], pa[ks], bb);
            }
        }
    }

    __syncthreads();
    for (int i = tid; i < 17 * 16; i += 128) {
        int m = i / 16, dq = i % 16;
        *(float4*)&s.pk[m][dq * 4] = *(const float4*)&pe_v[m * DH + dq * 4];
    }
    __syncthreads();

#pragma unroll
    for (int half_ = 0; half_ < 2; ++half_) {
        const int rl = rl0 + 8 * half_;
        const int tg = it * 64 + rl;
        const float l = lrow[half_];
        float wm[16], sumw = 0.f;
#pragma unroll
        for (int m = 0; m < 16; ++m) { wm[m] = s.wsum[rl][m]; sumw += wm[m]; }
        const float w0 = l - sumw;
        const float inv = 1.f / l;
#pragma unroll
        for (int nt = 0; nt < 8; ++nt) {
            const int d0 = nt * 8 + 2 * kq;
            float acc0 = o[nt][half_ * 2 + 0] + w0 * s.pk[0][d0];
            float acc1 = o[nt][half_ * 2 + 1] + w0 * s.pk[0][d0 + 1];
#pragma unroll
            for (int m = 1; m <= 16; ++m) {
                acc0 = fmaf(wm[m - 1], s.pk[m][d0], acc0);
                acc1 = fmaf(wm[m - 1], s.pk[m][d0 + 1], acc1);
            }
            *(__half2*)&g_att16[((size_t)(bidx * Tt) + tg) * Uu + hh * DH + d0] =
                __floats2half2_rn(acc0 * inv, acc1 * inv);
        }
    }
}

// ---------------------------------------------------------------------------
// Fused out-projection + residual + LayerNorm (r13/r15 winner, unchanged).
// ---------------------------------------------------------------------------
struct OProjSmem {
    uint32_t As[4][64][12];     // 12288 B [r][k-pair]
    uint32_t Bs[4][512][12];    // 98304 B [n][k-pair]
    float part[2][8][64];       // 4096 B
    float mu[64];
    float rs[64];
};

__global__ __launch_bounds__(256) void oproj_ln(
    const float* __restrict__ bo,
    const float* __restrict__ res,
    const float* __restrict__ gamma, const float* __restrict__ beta,
    float* __restrict__ out)
{
    extern __shared__ __align__(1024) char smem_raw[];
    OProjSmem& sm = *reinterpret_cast<OProjSmem*>(smem_raw);

    const int tid  = threadIdx.x;
    const int lane = tid & 31;
    const int w    = tid >> 5;
    const int kq   = lane & 3;
    const int ng   = lane >> 2;
    const int rowBase = blockIdx.x * 64;

    const __half* Wt = g_wt16[3];
    const uint32_t aS = smem_u32(&sm.As[0][0][0]);
    const uint32_t bS = smem_u32(&sm.Bs[0][0][0]);

    auto issue = [&](int s, int kt) {
        const int kb = kt * 16;
        if (tid < 128) {
            const int r = tid >> 1, c2 = tid & 1;
            cp16(aS + (((s * 64 + r) * 12 + c2 * 4) << 2),
                 &g_att16[(size_t)(rowBase + r) * Uu + kb + c2 * 8]);
        }
#pragma unroll
        for (int ii = 0; ii < 4; ++ii) {
            const int idx = tid + ii * 256;
            const int n = idx >> 1, c2 = idx & 1;
            cp16(bS + (((s * 512 + n) * 12 + c2 * 4) << 2),
                 &Wt[(size_t)n * Uu + kb + c2 * 8]);
        }
        asm volatile("cp.async.commit_group;");
    };

    constexpr int NIT = Uu / 16;   // 32
    issue(0, 0);
    issue(1, 1);
    issue(2, 2);

    float c[4][8][4] = {};

    for (int kb = 0; kb < NIT; ++kb) {
        const int cur = kb & 3;
        if      (kb + 2 < NIT) asm volatile("cp.async.wait_group 2;");
        else if (kb + 1 < NIT) asm volatile("cp.async.wait_group 1;");
        else                   asm volatile("cp.async.wait_group 0;");
        __syncthreads();

        uint32_t a[4][4];
#pragma unroll
        for (int mt = 0; mt < 4; ++mt) {
            const int r0 = mt * 16 + ng;
            a[mt][0] = sm.As[cur][r0][kq];
            a[mt][1] = sm.As[cur][r0 + 8][kq];
            a[mt][2] = sm.As[cur][r0][kq + 4];
            a[mt][3] = sm.As[cur][r0 + 8][kq + 4];
        }
#pragma unroll
        for (int nt = 0; nt < 8; ++nt) {
            uint32_t b[2];
            const int n0 = w * 64 + nt * 8 + ng;
            b[0] = sm.Bs[cur][n0][kq];
            b[1] = sm.Bs[cur][n0][kq + 4];
#pragma unroll
            for (int mt = 0; mt < 4; ++mt)
                mma_f16(c[mt][nt], a[mt], b);
        }

        if (kb + 3 < NIT) issue((kb + 3) & 3, kb + 3);
    }

    float psum[8] = {}, psq[8] = {};
#pragma unroll
    for (int mt = 0; mt < 4; ++mt) {
#pragma unroll
        for (int half_ = 0; half_ < 2; ++half_) {
            const int m = rowBase + mt * 16 + ng + half_ * 8;
            const int slot = mt * 2 + half_;
#pragma unroll
            for (int nt = 0; nt < 8; ++nt) {
                const int n = w * 64 + nt * 8 + 2 * kq;
                const float2 bi = *(const float2*)&bo[n];
                const float2 r2 = *(const float2*)&res[(size_t)m * Uu + n];
                float vx = fmaxf(c[mt][nt][half_ * 2 + 0] + bi.x, 0.f) + r2.x;
                float vy = fmaxf(c[mt][nt][half_ * 2 + 1] + bi.y, 0.f) + r2.y;
                c[mt][nt][half_ * 2 + 0] = vx;
                c[mt][nt][half_ * 2 + 1] = vy;
                psum[slot] += vx + vy;
                psq[slot]  += vx * vx + vy * vy;
            }
        }
    }
#pragma unroll
    for (int slot = 0; slot < 8; ++slot) {
        psum[slot] += __shfl_xor_sync(0xffffffffu, psum[slot], 1);
        psum[slot] += __shfl_xor_sync(0xffffffffu, psum[slot], 2);
        psq[slot]  += __shfl_xor_sync(0xffffffffu, psq[slot], 1);
        psq[slot]  += __shfl_xor_sync(0xffffffffu, psq[slot], 2);
    }
    if (kq == 0) {
#pragma unroll
        for (int mt = 0; mt < 4; ++mt)
#pragma unroll
            for (int half_ = 0; half_ < 2; ++half_) {
                const int rl = mt * 16 + ng + half_ * 8;
                sm.part[0][w][rl] = psum[mt * 2 + half_];
                sm.part[1][w][rl] = psq[mt * 2 + half_];
            }
    }
    __syncthreads();

    if (tid < 64) {
        float su = 0.f, sq = 0.f;
#pragma unroll
        for (int wi = 0; wi < 8; ++wi) {
            su += sm.part[0][wi][tid];
            sq += sm.part[1][wi][tid];
        }
        const float mu = su * (1.f / Uu);
        const float var = sq * (1.f / Uu) - mu * mu;
        sm.mu[tid] = mu;
        sm.rs[tid] = rsqrtf(var + 1e-3f);
    }
    __syncthreads();

#pragma unroll
    for (int mt = 0; mt < 4; ++mt) {
#pragma unroll
        for (int half_ = 0; half_ < 2; ++half_) {
            const int rl = mt * 16 + ng + half_ * 8;
            const int m = rowBase + rl;
            const float mu = sm.mu[rl];
            const float rstd = sm.rs[rl];
#pragma unroll
            for (int nt = 0; nt < 8; ++nt) {
                const int n = w * 64 + nt * 8 + 2 * kq;
                const float2 g2 = *(const float2*)&gamma[n];
                const float2 b2 = *(const float2*)&beta[n];
                float2 o;
                o.x = (c[mt][nt][half_ * 2 + 0] - mu) * rstd * g2.x + b2.x;
                o.y = (c[mt][nt][half_ * 2 + 1] - mu) * rstd * g2.y + b2.y;
                *(float2*)&out[(size_t)m * Uu + n] = o;
            }
        }
    }
}

// ---------------------------------------------------------------------------
extern "C" void kernel_launch(void* const* d_in, const int* in_sizes, int n_in,
                              void* d_out, int out_size) {
    (void)n_in; (void)out_size;

    int iq, ik, iv, iWq, ibq, iWk, ibk, iWv, ibv, iWo, ibo, ig, ibe, ipk, ipv;
    if (in_sizes[0] == Bb * Tt * Uu) {
        iq = 0; ik = 1; iv = 2; iWq = 3; ibq = 4; iWk = 5; ibk = 6;
        iWv = 7; ibv = 8; iWo = 9; ibo = 10; ig = 11; ibe = 12; ipk = 13; ipv = 14;
    } else if (in_sizes[0] == Uu * Uu) {
        iWk = 0; iWo = 1; iWq = 2; iWv = 3; ibe = 4; ibk = 5; ibo = 6;
        ibq = 7; ibv = 8; ig = 9; ik = 10; ipk = 11; ipv = 12; iq = 13; iv = 14;
    } else {
        ibe = 0; ibk = 1; ibo = 2; ibq = 3; ibv = 4; ig = 5; ik = 6;
        ipk = 7; ipv = 8; iq = 9; iv = 10; iWk = 11; iWo = 12; iWq = 13; iWv = 14;
    }

    const float* q    = (const float*)d_in[iq];
    const float* k    = (const float*)d_in[ik];
    const float* v    = (const float*)d_in[iv];
    const float* Wq   = (const float*)d_in[iWq];
    const float* bq   = (const float*)d_in[ibq];
    const float* Wk   = (const float*)d_in[iWk];
    const float* bk   = (const float*)d_in[ibk];
    const float* Wv   = (const float*)d_in[iWv];
    const float* bv   = (const float*)d_in[ibv];
    const float* Wo   = (const float*)d_in[iWo];
    const float* bo   = (const float*)d_in[ibo];
    const float* gamma= (const float*)d_in[ig];
    const float* beta = (const float*)d_in[ibe];
    const float* pek  = (const float*)d_in[ipk];
    const float* pev  = (const float*)d_in[ipv];
    float* out = (float*)d_out;

    cudaFuncSetAttribute(attn_kernel, cudaFuncAttributeMaxDynamicSharedMemorySize,
                         (int)sizeof(AttnSmem));
    cudaFuncSetAttribute(proj_gemm, cudaFuncAttributeMaxDynamicSharedMemorySize,
                         (int)sizeof(ProjSmem));
    cudaFuncSetAttribute(oproj_ln, cudaFuncAttributeMaxDynamicSharedMemorySize,
                         (int)sizeof(OProjSmem));

    // Convert inputs + weights to fp16 (weights transposed)
    cvt_in<<<dim3(MR * Uu / 4 / 512, 3), 512>>>(q, k, v);
    cvt_w<<<dim3(16, 16, 4), 256>>>(Wq, Wk, Wv, Wo);

    // Q/K/V projections (fp16 mma), head-split fp16 outputs
    proj_gemm<<<dim3(4, 64, 3), 256, sizeof(ProjSmem)>>>(bq, bk, bv);

    attn_kernel<<<dim3(16, 64), 128, sizeof(AttnSmem)>>>(pek, pev);

    // Fused output projection + residual + LayerNorm -> final fp32 output
    oproj_ln<<<128, 256, sizeof(OProjSmem)>>>(bo, q, gamma, beta, out);
}